// round 6
// baseline (speedup 1.0000x reference)
#include <cuda_runtime.h>
#include <cuda_bf16.h>

#define NN 10000
#define NE 640000
#define DD 128
#define ND (NN * DD)

// ---------------- device scratch (no allocations allowed) ----------------
__device__ int   g_is64;        // 1 if src/dst are int64, 0 if int32
__device__ int   g_indeg[NN];
__device__ int   g_outdeg[NN];
__device__ int   g_fill[NN];
__device__ int   g_row_start[NN + 1];
__device__ float g_norm_src[NN];
__device__ float g_norm_dst[NN];
__device__ int   g_col[NE];     // src node per edge, grouped by dst
__device__ float g_val[NE];     // norm_src[src] per edge
__device__ float g_agg[ND];     // SpMM output buffer

__device__ __forceinline__ int edge_idx(const void* p, int e, int is64) {
    if (is64) return (int)((const long long*)p)[e];
    return ((const int*)p)[e];
}

// ---------------- dtype detection ----------------
// Node ids < 10000 < 2^32: if buffer is int64, every odd 32-bit word is 0.
// Sample the first 512 odd words; P[all zero | genuine int32 ids] ~ 1e-2048.
__global__ void detect_kernel(const void* src) {
    __shared__ int any_nonzero;
    if (threadIdx.x == 0) any_nonzero = 0;
    __syncthreads();
    const int* w = (const int*)src;
#pragma unroll
    for (int it = 0; it < 2; it++) {
        int idx = 2 * (threadIdx.x + it * 256) + 1;
        if (w[idx] != 0) any_nonzero = 1;
    }
    __syncthreads();
    if (threadIdx.x == 0) g_is64 = any_nonzero ? 0 : 1;
}

// ---------------- graph build ----------------
__global__ void zero_counters() {
    int i = blockIdx.x * blockDim.x + threadIdx.x;
    if (i < NN) { g_indeg[i] = 0; g_outdeg[i] = 0; g_fill[i] = 0; }
}

__global__ void degrees_kernel(const void* __restrict__ src,
                               const void* __restrict__ dst) {
    int e = blockIdx.x * blockDim.x + threadIdx.x;
    int is64 = g_is64;
    if (e < NE) {
        int s = edge_idx(src, e, is64);
        int d = edge_idx(dst, e, is64);
        if ((unsigned)s < NN) atomicAdd(&g_outdeg[s], 1);
        if ((unsigned)d < NN) atomicAdd(&g_indeg[d], 1);
    }
}

__global__ void norms_kernel() {
    int i = blockIdx.x * blockDim.x + threadIdx.x;
    if (i < NN) {
        g_norm_src[i] = rsqrtf(fmaxf((float)g_outdeg[i], 1.0f));
        g_norm_dst[i] = rsqrtf(fmaxf((float)g_indeg[i], 1.0f));
    }
}

// Single-block exclusive scan of g_indeg -> g_row_start (10000 elements)
__global__ void scan_kernel() {
    __shared__ int ssum[1024];
    const int CH = 10;           // 1024 * 10 = 10240 >= NN
    int t = threadIdx.x;
    int base = t * CH;
    int v[CH];
    int s = 0;
#pragma unroll
    for (int i = 0; i < CH; i++) {
        int idx = base + i;
        v[i] = (idx < NN) ? g_indeg[idx] : 0;
        s += v[i];
    }
    ssum[t] = s;
    __syncthreads();
    for (int off = 1; off < 1024; off <<= 1) {
        int add = (t >= off) ? ssum[t - off] : 0;
        __syncthreads();
        ssum[t] += add;
        __syncthreads();
    }
    int run = (t > 0) ? ssum[t - 1] : 0;
#pragma unroll
    for (int i = 0; i < CH; i++) {
        int idx = base + i;
        if (idx < NN) g_row_start[idx] = run;
        run += v[i];
    }
    if (t == 1023) g_row_start[NN] = ssum[1023];
}

__global__ void fill_kernel(const void* __restrict__ src,
                            const void* __restrict__ dst) {
    int e = blockIdx.x * blockDim.x + threadIdx.x;
    int is64 = g_is64;
    if (e < NE) {
        int d = edge_idx(dst, e, is64);
        int s = edge_idx(src, e, is64);
        if ((unsigned)d < NN && (unsigned)s < NN) {
            int pos = g_row_start[d] + atomicAdd(&g_fill[d], 1);
            g_col[pos] = s;
            g_val[pos] = g_norm_src[s];
        }
    }
}

// ---------------- SpMM: one warp per destination row ----------------
// agg[r,:] = norm_dst[r] * sum_{j in row r} val[j] * X[col[j], :]
// Unroll x4 with front-batched loads for MLP over ~234cyc L2 latency.
__global__ void __launch_bounds__(512, 4) spmm_kernel(const float* __restrict__ X) {
    int warp = blockIdx.x * (blockDim.x >> 5) + (threadIdx.x >> 5);
    if (warp >= NN) return;
    int lane = threadIdx.x & 31;
    int j0 = g_row_start[warp];
    int j1 = g_row_start[warp + 1];
    const float4* __restrict__ Xv = (const float4*)X;

    float4 a0 = make_float4(0.f, 0.f, 0.f, 0.f);
    float4 a1 = make_float4(0.f, 0.f, 0.f, 0.f);
    float4 a2 = make_float4(0.f, 0.f, 0.f, 0.f);
    float4 a3 = make_float4(0.f, 0.f, 0.f, 0.f);

    int j = j0;
    for (; j + 4 <= j1; j += 4) {
        int   s0 = g_col[j + 0], s1 = g_col[j + 1], s2 = g_col[j + 2], s3 = g_col[j + 3];
        float n0 = g_val[j + 0], n1 = g_val[j + 1], n2 = g_val[j + 2], n3 = g_val[j + 3];
        float4 v0 = Xv[s0 * 32 + lane];
        float4 v1 = Xv[s1 * 32 + lane];
        float4 v2 = Xv[s2 * 32 + lane];
        float4 v3 = Xv[s3 * 32 + lane];
        a0.x += v0.x * n0; a0.y += v0.y * n0; a0.z += v0.z * n0; a0.w += v0.w * n0;
        a1.x += v1.x * n1; a1.y += v1.y * n1; a1.z += v1.z * n1; a1.w += v1.w * n1;
        a2.x += v2.x * n2; a2.y += v2.y * n2; a2.z += v2.z * n2; a2.w += v2.w * n2;
        a3.x += v3.x * n3; a3.y += v3.y * n3; a3.z += v3.z * n3; a3.w += v3.w * n3;
    }
    for (; j < j1; ++j) {
        int s = g_col[j];
        float nv = g_val[j];
        float4 v = Xv[s * 32 + lane];
        a0.x += v.x * nv; a0.y += v.y * nv; a0.z += v.z * nv; a0.w += v.w * nv;
    }

    float nd = g_norm_dst[warp];
    float4 acc;
    acc.x = (a0.x + a1.x + a2.x + a3.x) * nd;
    acc.y = (a0.y + a1.y + a2.y + a3.y) * nd;
    acc.z = (a0.z + a1.z + a2.z + a3.z) * nd;
    acc.w = (a0.w + a1.w + a2.w + a3.w) * nd;
    ((float4*)g_agg)[warp * 32 + lane] = acc;
}

// ---------------- GEMM: Y[M,128] = g_agg[M,128] @ W[128,128] + b (opt. ReLU)
// A operand is ALWAYS the device-global g_agg (never passed from host).
// 64x64 tile per block, 256 threads (16x16), 4x4 microtile per thread.
__global__ void __launch_bounds__(256, 4) gemm_kernel(const float* __restrict__ W,
                            const float* __restrict__ b,
                            float* __restrict__ Y,
                            int relu) {
    __shared__ float As[16][64];   // [k][row]
    __shared__ float Ws[16][64];   // [k][col]
    const float* __restrict__ A = g_agg;
    int t  = threadIdx.x;
    int tx = t & 15;
    int ty = t >> 4;
    int rb = blockIdx.x * 64;
    int cb = blockIdx.y * 64;

    float acc[4][4];
#pragma unroll
    for (int i = 0; i < 4; i++)
#pragma unroll
        for (int j = 0; j < 4; j++) acc[i][j] = 0.f;

    for (int kb = 0; kb < DD; kb += 16) {
        // load A tile: 64 rows x 16 k -> As[k][row]
#pragma unroll
        for (int it = 0; it < 4; it++) {
            int idx = t + it * 256;       // 0..1023
            int row = idx >> 4;
            int kk  = idx & 15;
            int gr  = rb + row;
            As[kk][row] = (gr < NN) ? A[gr * DD + kb + kk] : 0.f;
        }
        // load W tile: 16 k x 64 cols -> Ws[k][col]
#pragma unroll
        for (int it = 0; it < 4; it++) {
            int idx = t + it * 256;
            int k = idx >> 6;
            int c = idx & 63;
            Ws[k][c] = W[(kb + k) * DD + cb + c];
        }
        __syncthreads();
#pragma unroll
        for (int k = 0; k < 16; k++) {
            float4 a = *(const float4*)&As[k][ty * 4];
            float4 w = *(const float4*)&Ws[k][tx * 4];
            acc[0][0] += a.x * w.x; acc[0][1] += a.x * w.y; acc[0][2] += a.x * w.z; acc[0][3] += a.x * w.w;
            acc[1][0] += a.y * w.x; acc[1][1] += a.y * w.y; acc[1][2] += a.y * w.z; acc[1][3] += a.y * w.w;
            acc[2][0] += a.z * w.x; acc[2][1] += a.z * w.y; acc[2][2] += a.z * w.z; acc[2][3] += a.z * w.w;
            acc[3][0] += a.w * w.x; acc[3][1] += a.w * w.y; acc[3][2] += a.w * w.z; acc[3][3] += a.w * w.w;
        }
        __syncthreads();
    }

    int c0 = cb + tx * 4;
    float4 bias = *(const float4*)&b[c0];
#pragma unroll
    for (int i = 0; i < 4; i++) {
        int r = rb + ty * 4 + i;
        if (r < NN) {
            float4 o;
            o.x = acc[i][0] + bias.x;
            o.y = acc[i][1] + bias.y;
            o.z = acc[i][2] + bias.z;
            o.w = acc[i][3] + bias.w;
            if (relu) {
                o.x = fmaxf(o.x, 0.f); o.y = fmaxf(o.y, 0.f);
                o.z = fmaxf(o.z, 0.f); o.w = fmaxf(o.w, 0.f);
            }
            *(float4*)&Y[r * DD + c0] = o;
        }
    }
}

// ---------------- launch ----------------
extern "C" void kernel_launch(void* const* d_in, const int* in_sizes, int n_in,
                              void* d_out, int out_size) {
    const float* x   = (const float*)d_in[0];
    const void*  src = d_in[1];   // int32 or int64 — detected on device
    const void*  dst = d_in[2];
    const float* W[6] = { (const float*)d_in[3], (const float*)d_in[5],
                          (const float*)d_in[7], (const float*)d_in[9],
                          (const float*)d_in[11], (const float*)d_in[13] };
    const float* B[6] = { (const float*)d_in[4], (const float*)d_in[6],
                          (const float*)d_in[8], (const float*)d_in[10],
                          (const float*)d_in[12], (const float*)d_in[14] };
    float* out = (float*)d_out;

    // output layout: (h6, h5, h4, h3, h2, h1)
    float* h[6];
    for (int i = 0; i < 6; i++) h[i] = out + (size_t)(5 - i) * ND;  // h[0]=h1 ... h[5]=h6

    // graph build
    detect_kernel<<<1, 256>>>(src);
    zero_counters<<<(NN + 255) / 256, 256>>>();
    degrees_kernel<<<(NE + 255) / 256, 256>>>(src, dst);
    norms_kernel<<<(NN + 255) / 256, 256>>>();
    scan_kernel<<<1, 1024>>>();
    fill_kernel<<<(NE + 255) / 256, 256>>>(src, dst);

    dim3 gemm_grid((NN + 63) / 64, 2);
    const int SPMM_BLK = 512;                      // 16 warps/block
    int spmm_grid = (NN * 32 + SPMM_BLK - 1) / SPMM_BLK;

    const float* in = x;
    for (int layer = 0; layer < 6; layer++) {
        spmm_kernel<<<spmm_grid, SPMM_BLK>>>(in);
        gemm_kernel<<<gemm_grid, 256>>>(W[layer], B[layer], h[layer],
                                        layer < 5 ? 1 : 0);
        in = h[layer];
    }
}

// round 10
// speedup vs baseline: 1.5780x; 1.5780x over previous
#include <cuda_runtime.h>
#include <cuda_bf16.h>

#define NN 10000
#define NE 640000
#define DD 128
#define ND (NN * DD)

// ---------------- device scratch (no allocations allowed) ----------------
__device__ int   g_is64;        // 1 if src/dst are int64, 0 if int32
__device__ int   g_indeg[NN];
__device__ int   g_outdeg[NN];
__device__ int   g_fill[NN];
__device__ int   g_row_start[NN + 1];
__device__ float g_norm_src[NN];
__device__ float g_norm_dst[NN];
__device__ int2  g_edge[NE];    // (src node, norm_src bits) per edge, grouped by dst
__device__ float g_agg[ND];     // SpMM output buffer

__device__ __forceinline__ int edge_idx(const void* p, int e, int is64) {
    if (is64) return (int)((const long long*)p)[e];
    return ((const int*)p)[e];
}

// ---------------- dtype detection ----------------
// Node ids < 10000 < 2^32: if buffer is int64, every odd 32-bit word is 0.
__global__ void detect_kernel(const void* src) {
    __shared__ int any_nonzero;
    if (threadIdx.x == 0) any_nonzero = 0;
    __syncthreads();
    const int* w = (const int*)src;
#pragma unroll
    for (int it = 0; it < 2; it++) {
        int idx = 2 * (threadIdx.x + it * 256) + 1;
        if (w[idx] != 0) any_nonzero = 1;
    }
    __syncthreads();
    if (threadIdx.x == 0) g_is64 = any_nonzero ? 0 : 1;
}

// ---------------- graph build ----------------
__global__ void zero_counters() {
    int i = blockIdx.x * blockDim.x + threadIdx.x;
    if (i < NN) { g_indeg[i] = 0; g_outdeg[i] = 0; g_fill[i] = 0; }
}

__global__ void degrees_kernel(const void* __restrict__ src,
                               const void* __restrict__ dst) {
    int e = blockIdx.x * blockDim.x + threadIdx.x;
    int is64 = g_is64;
    if (e < NE) {
        int s = edge_idx(src, e, is64);
        int d = edge_idx(dst, e, is64);
        if ((unsigned)s < NN) atomicAdd(&g_outdeg[s], 1);
        if ((unsigned)d < NN) atomicAdd(&g_indeg[d], 1);
    }
}

__global__ void norms_kernel() {
    int i = blockIdx.x * blockDim.x + threadIdx.x;
    if (i < NN) {
        g_norm_src[i] = rsqrtf(fmaxf((float)g_outdeg[i], 1.0f));
        g_norm_dst[i] = rsqrtf(fmaxf((float)g_indeg[i], 1.0f));
    }
}

// Single-block exclusive scan of g_indeg -> g_row_start (10000 elements)
__global__ void scan_kernel() {
    __shared__ int ssum[1024];
    const int CH = 10;           // 1024 * 10 = 10240 >= NN
    int t = threadIdx.x;
    int base = t * CH;
    int v[CH];
    int s = 0;
#pragma unroll
    for (int i = 0; i < CH; i++) {
        int idx = base + i;
        v[i] = (idx < NN) ? g_indeg[idx] : 0;
        s += v[i];
    }
    ssum[t] = s;
    __syncthreads();
    for (int off = 1; off < 1024; off <<= 1) {
        int add = (t >= off) ? ssum[t - off] : 0;
        __syncthreads();
        ssum[t] += add;
        __syncthreads();
    }
    int run = (t > 0) ? ssum[t - 1] : 0;
#pragma unroll
    for (int i = 0; i < CH; i++) {
        int idx = base + i;
        if (idx < NN) g_row_start[idx] = run;
        run += v[i];
    }
    if (t == 1023) g_row_start[NN] = ssum[1023];
}

__global__ void fill_kernel(const void* __restrict__ src,
                            const void* __restrict__ dst) {
    int e = blockIdx.x * blockDim.x + threadIdx.x;
    int is64 = g_is64;
    if (e < NE) {
        int d = edge_idx(dst, e, is64);
        int s = edge_idx(src, e, is64);
        if ((unsigned)d < NN && (unsigned)s < NN) {
            int pos = g_row_start[d] + atomicAdd(&g_fill[d], 1);
            g_edge[pos] = make_int2(s, __float_as_int(g_norm_src[s]));
        }
    }
}

// ---------------- SpMM: one warp per destination row ----------------
// agg[r,:] = norm_dst[r] * sum_{j in row r} val[j] * X[col[j], :]
// Unroll x8, no reg cap: ~8 gather loads in flight per warp over ~234cyc L2.
__global__ void __launch_bounds__(256) spmm_kernel(const float* __restrict__ X) {
    int warp = blockIdx.x * (blockDim.x >> 5) + (threadIdx.x >> 5);
    if (warp >= NN) return;
    int lane = threadIdx.x & 31;
    int j0 = g_row_start[warp];
    int j1 = g_row_start[warp + 1];
    const float4* __restrict__ Xv = (const float4*)X;
    const int2*   __restrict__ Ev = g_edge;

    float4 a0 = make_float4(0.f, 0.f, 0.f, 0.f);
    float4 a1 = make_float4(0.f, 0.f, 0.f, 0.f);
    float4 a2 = make_float4(0.f, 0.f, 0.f, 0.f);
    float4 a3 = make_float4(0.f, 0.f, 0.f, 0.f);

    int j = j0;
    for (; j + 8 <= j1; j += 8) {
        int2 e0 = Ev[j + 0], e1 = Ev[j + 1], e2 = Ev[j + 2], e3 = Ev[j + 3];
        int2 e4 = Ev[j + 4], e5 = Ev[j + 5], e6 = Ev[j + 6], e7 = Ev[j + 7];
        float4 v0 = Xv[e0.x * 32 + lane];
        float4 v1 = Xv[e1.x * 32 + lane];
        float4 v2 = Xv[e2.x * 32 + lane];
        float4 v3 = Xv[e3.x * 32 + lane];
        float4 v4 = Xv[e4.x * 32 + lane];
        float4 v5 = Xv[e5.x * 32 + lane];
        float4 v6 = Xv[e6.x * 32 + lane];
        float4 v7 = Xv[e7.x * 32 + lane];
        float n0 = __int_as_float(e0.y), n1 = __int_as_float(e1.y);
        float n2 = __int_as_float(e2.y), n3 = __int_as_float(e3.y);
        float n4 = __int_as_float(e4.y), n5 = __int_as_float(e5.y);
        float n6 = __int_as_float(e6.y), n7 = __int_as_float(e7.y);
        a0.x += v0.x * n0; a0.y += v0.y * n0; a0.z += v0.z * n0; a0.w += v0.w * n0;
        a1.x += v1.x * n1; a1.y += v1.y * n1; a1.z += v1.z * n1; a1.w += v1.w * n1;
        a2.x += v2.x * n2; a2.y += v2.y * n2; a2.z += v2.z * n2; a2.w += v2.w * n2;
        a3.x += v3.x * n3; a3.y += v3.y * n3; a3.z += v3.z * n3; a3.w += v3.w * n3;
        a0.x += v4.x * n4; a0.y += v4.y * n4; a0.z += v4.z * n4; a0.w += v4.w * n4;
        a1.x += v5.x * n5; a1.y += v5.y * n5; a1.z += v5.z * n5; a1.w += v5.w * n5;
        a2.x += v6.x * n6; a2.y += v6.y * n6; a2.z += v6.z * n6; a2.w += v6.w * n6;
        a3.x += v7.x * n7; a3.y += v7.y * n7; a3.z += v7.z * n7; a3.w += v7.w * n7;
    }
    for (; j < j1; ++j) {
        int2 e = Ev[j];
        float nv = __int_as_float(e.y);
        float4 v = Xv[e.x * 32 + lane];
        a0.x += v.x * nv; a0.y += v.y * nv; a0.z += v.z * nv; a0.w += v.w * nv;
    }

    float nd = g_norm_dst[warp];
    float4 acc;
    acc.x = (a0.x + a1.x + a2.x + a3.x) * nd;
    acc.y = (a0.y + a1.y + a2.y + a3.y) * nd;
    acc.z = (a0.z + a1.z + a2.z + a3.z) * nd;
    acc.w = (a0.w + a1.w + a2.w + a3.w) * nd;
    ((float4*)g_agg)[warp * 32 + lane] = acc;
}

// ---------------- GEMM: Y[M,128] = g_agg[M,128] @ W[128,128] + b (opt. ReLU)
// A operand is ALWAYS the device-global g_agg (never passed from host).
// 64x64 tile per block, 256 threads (16x16), 4x4 microtile per thread.
__global__ void __launch_bounds__(256, 4) gemm_kernel(const float* __restrict__ W,
                            const float* __restrict__ b,
                            float* __restrict__ Y,
                            int relu) {
    __shared__ float As[16][64];   // [k][row]
    __shared__ float Ws[16][64];   // [k][col]
    const float* __restrict__ A = g_agg;
    int t  = threadIdx.x;
    int tx = t & 15;
    int ty = t >> 4;
    int rb = blockIdx.x * 64;
    int cb = blockIdx.y * 64;

    float acc[4][4];
#pragma unroll
    for (int i = 0; i < 4; i++)
#pragma unroll
        for (int j = 0; j < 4; j++) acc[i][j] = 0.f;

    for (int kb = 0; kb < DD; kb += 16) {
        // load A tile: 64 rows x 16 k -> As[k][row]
#pragma unroll
        for (int it = 0; it < 4; it++) {
            int idx = t + it * 256;       // 0..1023
            int row = idx >> 4;
            int kk  = idx & 15;
            int gr  = rb + row;
            As[kk][row] = (gr < NN) ? A[gr * DD + kb + kk] : 0.f;
        }
        // load W tile: 16 k x 64 cols -> Ws[k][col]
#pragma unroll
        for (int it = 0; it < 4; it++) {
            int idx = t + it * 256;
            int k = idx >> 6;
            int c = idx & 63;
            Ws[k][c] = W[(kb + k) * DD + cb + c];
        }
        __syncthreads();
#pragma unroll
        for (int k = 0; k < 16; k++) {
            float4 a = *(const float4*)&As[k][ty * 4];
            float4 w = *(const float4*)&Ws[k][tx * 4];
            acc[0][0] += a.x * w.x; acc[0][1] += a.x * w.y; acc[0][2] += a.x * w.z; acc[0][3] += a.x * w.w;
            acc[1][0] += a.y * w.x; acc[1][1] += a.y * w.y; acc[1][2] += a.y * w.z; acc[1][3] += a.y * w.w;
            acc[2][0] += a.z * w.x; acc[2][1] += a.z * w.y; acc[2][2] += a.z * w.z; acc[2][3] += a.z * w.w;
            acc[3][0] += a.w * w.x; acc[3][1] += a.w * w.y; acc[3][2] += a.w * w.z; acc[3][3] += a.w * w.w;
        }
        __syncthreads();
    }

    int c0 = cb + tx * 4;
    float4 bias = *(const float4*)&b[c0];
#pragma unroll
    for (int i = 0; i < 4; i++) {
        int r = rb + ty * 4 + i;
        if (r < NN) {
            float4 o;
            o.x = acc[i][0] + bias.x;
            o.y = acc[i][1] + bias.y;
            o.z = acc[i][2] + bias.z;
            o.w = acc[i][3] + bias.w;
            if (relu) {
                o.x = fmaxf(o.x, 0.f); o.y = fmaxf(o.y, 0.f);
                o.z = fmaxf(o.z, 0.f); o.w = fmaxf(o.w, 0.f);
            }
            *(float4*)&Y[r * DD + c0] = o;
        }
    }
}

// ---------------- launch ----------------
extern "C" void kernel_launch(void* const* d_in, const int* in_sizes, int n_in,
                              void* d_out, int out_size) {
    const float* x   = (const float*)d_in[0];
    const void*  src = d_in[1];   // int32 or int64 — detected on device
    const void*  dst = d_in[2];
    const float* W[6] = { (const float*)d_in[3], (const float*)d_in[5],
                          (const float*)d_in[7], (const float*)d_in[9],
                          (const float*)d_in[11], (const float*)d_in[13] };
    const float* B[6] = { (const float*)d_in[4], (const float*)d_in[6],
                          (const float*)d_in[8], (const float*)d_in[10],
                          (const float*)d_in[12], (const float*)d_in[14] };
    float* out = (float*)d_out;

    // output layout: (h6, h5, h4, h3, h2, h1)
    float* h[6];
    for (int i = 0; i < 6; i++) h[i] = out + (size_t)(5 - i) * ND;  // h[0]=h1 ... h[5]=h6

    // graph build
    detect_kernel<<<1, 256>>>(src);
    zero_counters<<<(NN + 255) / 256, 256>>>();
    degrees_kernel<<<(NE + 255) / 256, 256>>>(src, dst);
    norms_kernel<<<(NN + 255) / 256, 256>>>();
    scan_kernel<<<1, 1024>>>();
    fill_kernel<<<(NE + 255) / 256, 256>>>(src, dst);

    dim3 gemm_grid((NN + 63) / 64, 2);
    const int SPMM_BLK = 256;                      // 8 warps/block, no reg cap
    int spmm_grid = (NN * 32 + SPMM_BLK - 1) / SPMM_BLK;

    const float* in = x;
    for (int layer = 0; layer < 6; layer++) {
        spmm_kernel<<<spmm_grid, SPMM_BLK>>>(in);
        gemm_kernel<<<gemm_grid, 256>>>(W[layer], B[layer], h[layer],
                                        layer < 5 ? 1 : 0);
        in = h[layer];
    }
}

// round 14
// speedup vs baseline: 1.6345x; 1.0358x over previous
#include <cuda_runtime.h>
#include <cuda_bf16.h>

#define NN 10000
#define NE 640000
#define DD 128
#define ND (NN * DD)

// ---------------- device scratch (no allocations allowed) ----------------
__device__ int   g_is64;        // 1 if src/dst are int64, 0 if int32
__device__ int   g_indeg[NN];
__device__ int   g_outdeg[NN];
__device__ int   g_fill[NN];
__device__ int   g_row_start[NN + 1];
__device__ float g_norm_src[NN];
__device__ float g_norm_dst[NN];
__device__ int2  g_edge[NE];    // (src node, norm_src bits) per edge, grouped by dst
__device__ float g_agg[ND];     // SpMM output buffer
__device__ uint2 g_x16[NN * 32]; // bf16 copy of previous layer output (128 bf16/row)

__device__ __forceinline__ int edge_idx(const void* p, int e, int is64) {
    if (is64) return (int)((const long long*)p)[e];
    return ((const int*)p)[e];
}

// ---------------- dtype detection ----------------
// Node ids < 10000 < 2^32: if buffer is int64, every odd 32-bit word is 0.
__global__ void detect_kernel(const void* src) {
    __shared__ int any_nonzero;
    if (threadIdx.x == 0) any_nonzero = 0;
    __syncthreads();
    const int* w = (const int*)src;
#pragma unroll
    for (int it = 0; it < 2; it++) {
        int idx = 2 * (threadIdx.x + it * 256) + 1;
        if (w[idx] != 0) any_nonzero = 1;
    }
    __syncthreads();
    if (threadIdx.x == 0) g_is64 = any_nonzero ? 0 : 1;
}

// ---------------- graph build ----------------
__global__ void zero_counters() {
    int i = blockIdx.x * blockDim.x + threadIdx.x;
    if (i < NN) { g_indeg[i] = 0; g_outdeg[i] = 0; g_fill[i] = 0; }
}

__global__ void degrees_kernel(const void* __restrict__ src,
                               const void* __restrict__ dst) {
    int e = blockIdx.x * blockDim.x + threadIdx.x;
    int is64 = g_is64;
    if (e < NE) {
        int s = edge_idx(src, e, is64);
        int d = edge_idx(dst, e, is64);
        if ((unsigned)s < NN) atomicAdd(&g_outdeg[s], 1);
        if ((unsigned)d < NN) atomicAdd(&g_indeg[d], 1);
    }
}

__global__ void norms_kernel() {
    int i = blockIdx.x * blockDim.x + threadIdx.x;
    if (i < NN) {
        g_norm_src[i] = rsqrtf(fmaxf((float)g_outdeg[i], 1.0f));
        g_norm_dst[i] = rsqrtf(fmaxf((float)g_indeg[i], 1.0f));
    }
}

// Single-block exclusive scan of g_indeg -> g_row_start (10000 elements)
__global__ void scan_kernel() {
    __shared__ int ssum[1024];
    const int CH = 10;           // 1024 * 10 = 10240 >= NN
    int t = threadIdx.x;
    int base = t * CH;
    int v[CH];
    int s = 0;
#pragma unroll
    for (int i = 0; i < CH; i++) {
        int idx = base + i;
        v[i] = (idx < NN) ? g_indeg[idx] : 0;
        s += v[i];
    }
    ssum[t] = s;
    __syncthreads();
    for (int off = 1; off < 1024; off <<= 1) {
        int add = (t >= off) ? ssum[t - off] : 0;
        __syncthreads();
        ssum[t] += add;
        __syncthreads();
    }
    int run = (t > 0) ? ssum[t - 1] : 0;
#pragma unroll
    for (int i = 0; i < CH; i++) {
        int idx = base + i;
        if (idx < NN) g_row_start[idx] = run;
        run += v[i];
    }
    if (t == 1023) g_row_start[NN] = ssum[1023];
}

__global__ void fill_kernel(const void* __restrict__ src,
                            const void* __restrict__ dst) {
    int e = blockIdx.x * blockDim.x + threadIdx.x;
    int is64 = g_is64;
    if (e < NE) {
        int d = edge_idx(dst, e, is64);
        int s = edge_idx(src, e, is64);
        if ((unsigned)d < NN && (unsigned)s < NN) {
            int pos = g_row_start[d] + atomicAdd(&g_fill[d], 1);
            g_edge[pos] = make_int2(s, __float_as_int(g_norm_src[s]));
        }
    }
}

// ---------------- SpMM (fp32 gather): layer 1 only ----------------------
// x is zero-mean, so bf16 quantization error would NOT average down in the
// segment sum (random-walk). Full fp32 keeps h1 exact.
__global__ void __launch_bounds__(256) spmm_fp32_kernel(const float* __restrict__ X) {
    int warp = blockIdx.x * (blockDim.x >> 5) + (threadIdx.x >> 5);
    if (warp >= NN) return;
    int lane = threadIdx.x & 31;
    int j0 = g_row_start[warp];
    int j1 = g_row_start[warp + 1];
    const float4* __restrict__ Xv = (const float4*)X;
    const int2*   __restrict__ Ev = g_edge;

    float4 a0 = make_float4(0.f, 0.f, 0.f, 0.f);
    float4 a1 = make_float4(0.f, 0.f, 0.f, 0.f);
    float4 a2 = make_float4(0.f, 0.f, 0.f, 0.f);
    float4 a3 = make_float4(0.f, 0.f, 0.f, 0.f);

    int j = j0;
    for (; j + 8 <= j1; j += 8) {
        int2 e0 = Ev[j + 0], e1 = Ev[j + 1], e2 = Ev[j + 2], e3 = Ev[j + 3];
        int2 e4 = Ev[j + 4], e5 = Ev[j + 5], e6 = Ev[j + 6], e7 = Ev[j + 7];
        float4 v0 = Xv[e0.x * 32 + lane];
        float4 v1 = Xv[e1.x * 32 + lane];
        float4 v2 = Xv[e2.x * 32 + lane];
        float4 v3 = Xv[e3.x * 32 + lane];
        float4 v4 = Xv[e4.x * 32 + lane];
        float4 v5 = Xv[e5.x * 32 + lane];
        float4 v6 = Xv[e6.x * 32 + lane];
        float4 v7 = Xv[e7.x * 32 + lane];
        float n0 = __int_as_float(e0.y), n1 = __int_as_float(e1.y);
        float n2 = __int_as_float(e2.y), n3 = __int_as_float(e3.y);
        float n4 = __int_as_float(e4.y), n5 = __int_as_float(e5.y);
        float n6 = __int_as_float(e6.y), n7 = __int_as_float(e7.y);
        a0.x += v0.x * n0; a0.y += v0.y * n0; a0.z += v0.z * n0; a0.w += v0.w * n0;
        a1.x += v1.x * n1; a1.y += v1.y * n1; a1.z += v1.z * n1; a1.w += v1.w * n1;
        a2.x += v2.x * n2; a2.y += v2.y * n2; a2.z += v2.z * n2; a2.w += v2.w * n2;
        a3.x += v3.x * n3; a3.y += v3.y * n3; a3.z += v3.z * n3; a3.w += v3.w * n3;
        a0.x += v4.x * n4; a0.y += v4.y * n4; a0.z += v4.z * n4; a0.w += v4.w * n4;
        a1.x += v5.x * n5; a1.y += v5.y * n5; a1.z += v5.z * n5; a1.w += v5.w * n5;
        a2.x += v6.x * n6; a2.y += v6.y * n6; a2.z += v6.z * n6; a2.w += v6.w * n6;
        a3.x += v7.x * n7; a3.y += v7.y * n7; a3.z += v7.z * n7; a3.w += v7.w * n7;
    }
    for (; j < j1; ++j) {
        int2 e = Ev[j];
        float nv = __int_as_float(e.y);
        float4 v = Xv[e.x * 32 + lane];
        a0.x += v.x * nv; a0.y += v.y * nv; a0.z += v.z * nv; a0.w += v.w * nv;
    }

    float nd = g_norm_dst[warp];
    float4 acc;
    acc.x = (a0.x + a1.x + a2.x + a3.x) * nd;
    acc.y = (a0.y + a1.y + a2.y + a3.y) * nd;
    acc.z = (a0.z + a1.z + a2.z + a3.z) * nd;
    acc.w = (a0.w + a1.w + a2.w + a3.w) * nd;
    ((float4*)g_agg)[warp * 32 + lane] = acc;
}

// ---------------- SpMM (bf16 gather): layers 2-6 ------------------------
// Inputs are ReLU outputs (non-negative) -> coherent segment sums average
// bf16 noise down (~eps/sqrt(deg)); measured 2.4e-4..5.3e-4 per output.
__global__ void __launch_bounds__(256) spmm_bf16_kernel() {
    int warp = blockIdx.x * (blockDim.x >> 5) + (threadIdx.x >> 5);
    if (warp >= NN) return;
    int lane = threadIdx.x & 31;
    int j0 = g_row_start[warp];
    int j1 = g_row_start[warp + 1];
    const uint2* __restrict__ Xv = g_x16;
    const int2*  __restrict__ Ev = g_edge;

    float4 a0 = make_float4(0.f, 0.f, 0.f, 0.f);
    float4 a1 = make_float4(0.f, 0.f, 0.f, 0.f);
    float4 a2 = make_float4(0.f, 0.f, 0.f, 0.f);
    float4 a3 = make_float4(0.f, 0.f, 0.f, 0.f);

    int j = j0;
    for (; j + 8 <= j1; j += 8) {
        int2 e0 = Ev[j + 0], e1 = Ev[j + 1], e2 = Ev[j + 2], e3 = Ev[j + 3];
        int2 e4 = Ev[j + 4], e5 = Ev[j + 5], e6 = Ev[j + 6], e7 = Ev[j + 7];
        uint2 v0 = Xv[e0.x * 32 + lane];
        uint2 v1 = Xv[e1.x * 32 + lane];
        uint2 v2 = Xv[e2.x * 32 + lane];
        uint2 v3 = Xv[e3.x * 32 + lane];
        uint2 v4 = Xv[e4.x * 32 + lane];
        uint2 v5 = Xv[e5.x * 32 + lane];
        uint2 v6 = Xv[e6.x * 32 + lane];
        uint2 v7 = Xv[e7.x * 32 + lane];
        float n0 = __int_as_float(e0.y), n1 = __int_as_float(e1.y);
        float n2 = __int_as_float(e2.y), n3 = __int_as_float(e3.y);
        float n4 = __int_as_float(e4.y), n5 = __int_as_float(e5.y);
        float n6 = __int_as_float(e6.y), n7 = __int_as_float(e7.y);
#define ACC(A, V, NV) { \
        float2 lo = __bfloat1622float2(*(__nv_bfloat162*)&(V).x); \
        float2 hi = __bfloat1622float2(*(__nv_bfloat162*)&(V).y); \
        (A).x += lo.x * (NV); (A).y += lo.y * (NV); \
        (A).z += hi.x * (NV); (A).w += hi.y * (NV); }
        ACC(a0, v0, n0) ACC(a1, v1, n1) ACC(a2, v2, n2) ACC(a3, v3, n3)
        ACC(a0, v4, n4) ACC(a1, v5, n5) ACC(a2, v6, n6) ACC(a3, v7, n7)
    }
    for (; j < j1; ++j) {
        int2 e = Ev[j];
        float nv = __int_as_float(e.y);
        uint2 v = Xv[e.x * 32 + lane];
        ACC(a0, v, nv)
    }
#undef ACC

    float nd = g_norm_dst[warp];
    float4 acc;
    acc.x = (a0.x + a1.x + a2.x + a3.x) * nd;
    acc.y = (a0.y + a1.y + a2.y + a3.y) * nd;
    acc.z = (a0.z + a1.z + a2.z + a3.z) * nd;
    acc.w = (a0.w + a1.w + a2.w + a3.w) * nd;
    ((float4*)g_agg)[warp * 32 + lane] = acc;
}

// ---------------- GEMM: Y[M,128] = g_agg[M,128] @ W[128,128] + b (opt. ReLU)
// Epilogue also writes the bf16 copy (g_x16) for the next layer's gather.
// 64x64 tile per block, 256 threads (16x16), 4x4 microtile per thread.
__global__ void __launch_bounds__(256, 4) gemm_kernel(const float* __restrict__ W,
                            const float* __restrict__ b,
                            float* __restrict__ Y,
                            int relu) {
    __shared__ float As[16][64];   // [k][row]
    __shared__ float Ws[16][64];   // [k][col]
    const float* __restrict__ A = g_agg;
    int t  = threadIdx.x;
    int tx = t & 15;
    int ty = t >> 4;
    int rb = blockIdx.x * 64;
    int cb = blockIdx.y * 64;

    float acc[4][4];
#pragma unroll
    for (int i = 0; i < 4; i++)
#pragma unroll
        for (int j = 0; j < 4; j++) acc[i][j] = 0.f;

    for (int kb = 0; kb < DD; kb += 16) {
        // load A tile: 64 rows x 16 k -> As[k][row]
#pragma unroll
        for (int it = 0; it < 4; it++) {
            int idx = t + it * 256;       // 0..1023
            int row = idx >> 4;
            int kk  = idx & 15;
            int gr  = rb + row;
            As[kk][row] = (gr < NN) ? A[gr * DD + kb + kk] : 0.f;
        }
        // load W tile: 16 k x 64 cols -> Ws[k][col]
#pragma unroll
        for (int it = 0; it < 4; it++) {
            int idx = t + it * 256;
            int k = idx >> 6;
            int c = idx & 63;
            Ws[k][c] = W[(kb + k) * DD + cb + c];
        }
        __syncthreads();
#pragma unroll
        for (int k = 0; k < 16; k++) {
            float4 a = *(const float4*)&As[k][ty * 4];
            float4 w = *(const float4*)&Ws[k][tx * 4];
            acc[0][0] += a.x * w.x; acc[0][1] += a.x * w.y; acc[0][2] += a.x * w.z; acc[0][3] += a.x * w.w;
            acc[1][0] += a.y * w.x; acc[1][1] += a.y * w.y; acc[1][2] += a.y * w.z; acc[1][3] += a.y * w.w;
            acc[2][0] += a.z * w.x; acc[2][1] += a.z * w.y; acc[2][2] += a.z * w.z; acc[2][3] += a.z * w.w;
            acc[3][0] += a.w * w.x; acc[3][1] += a.w * w.y; acc[3][2] += a.w * w.z; acc[3][3] += a.w * w.w;
        }
        __syncthreads();
    }

    int c0 = cb + tx * 4;
    float4 bias = *(const float4*)&b[c0];
#pragma unroll
    for (int i = 0; i < 4; i++) {
        int r = rb + ty * 4 + i;
        if (r < NN) {
            float4 o;
            o.x = acc[i][0] + bias.x;
            o.y = acc[i][1] + bias.y;
            o.z = acc[i][2] + bias.z;
            o.w = acc[i][3] + bias.w;
            if (relu) {
                o.x = fmaxf(o.x, 0.f); o.y = fmaxf(o.y, 0.f);
                o.z = fmaxf(o.z, 0.f); o.w = fmaxf(o.w, 0.f);
            }
            *(float4*)&Y[r * DD + c0] = o;
            // bf16 copy for next layer's gather
            __nv_bfloat162 b0 = __float22bfloat162_rn(make_float2(o.x, o.y));
            __nv_bfloat162 b1 = __float22bfloat162_rn(make_float2(o.z, o.w));
            uint2 pk;
            pk.x = *(unsigned*)&b0;
            pk.y = *(unsigned*)&b1;
            g_x16[r * 32 + (c0 >> 2)] = pk;
        }
    }
}

// ---------------- launch ----------------
extern "C" void kernel_launch(void* const* d_in, const int* in_sizes, int n_in,
                              void* d_out, int out_size) {
    const float* x   = (const float*)d_in[0];
    const void*  src = d_in[1];   // int32 or int64 — detected on device
    const void*  dst = d_in[2];
    const float* W[6] = { (const float*)d_in[3], (const float*)d_in[5],
                          (const float*)d_in[7], (const float*)d_in[9],
                          (const float*)d_in[11], (const float*)d_in[13] };
    const float* B[6] = { (const float*)d_in[4], (const float*)d_in[6],
                          (const float*)d_in[8], (const float*)d_in[10],
                          (const float*)d_in[12], (const float*)d_in[14] };
    float* out = (float*)d_out;

    // output layout: (h6, h5, h4, h3, h2, h1)
    float* h[6];
    for (int i = 0; i < 6; i++) h[i] = out + (size_t)(5 - i) * ND;  // h[0]=h1 ... h[5]=h6

    // graph build
    detect_kernel<<<1, 256>>>(src);
    zero_counters<<<(NN + 255) / 256, 256>>>();
    degrees_kernel<<<(NE + 255) / 256, 256>>>(src, dst);
    norms_kernel<<<(NN + 255) / 256, 256>>>();
    scan_kernel<<<1, 1024>>>();
    fill_kernel<<<(NE + 255) / 256, 256>>>(src, dst);

    dim3 gemm_grid((NN + 63) / 64, 2);
    const int SPMM_BLK = 256;                      // 8 warps/block
    int spmm_grid = (NN * 32 + SPMM_BLK - 1) / SPMM_BLK;

    for (int layer = 0; layer < 6; layer++) {
        if (layer == 0)
            spmm_fp32_kernel<<<spmm_grid, SPMM_BLK>>>(x);
        else
            spmm_bf16_kernel<<<spmm_grid, SPMM_BLK>>>();
        gemm_kernel<<<gemm_grid, 256>>>(W[layer], B[layer], h[layer],
                                        layer < 5 ? 1 : 0);
    }
}

// round 15
// speedup vs baseline: 1.6377x; 1.0019x over previous
#include <cuda_runtime.h>
#include <cuda_bf16.h>

#define NN 10000
#define NE 640000
#define DD 128
#define ND (NN * DD)

// ---------------- device scratch (no allocations allowed) ----------------
__device__ int   g_is64;        // 1 if src/dst are int64, 0 if int32
__device__ int   g_indeg[NN];
__device__ int   g_outdeg[NN];
__device__ int   g_fill[NN];
__device__ int   g_row_start[NN + 1];
__device__ float g_norm_src[NN];
__device__ float g_norm_dst[NN];
__device__ int2  g_edge[NE];    // (src node, norm_src bits) per edge, grouped by dst
__device__ float g_agg[ND];     // SpMM output buffer
__device__ uint2 g_x16[NN * 32]; // bf16 copy of previous layer output (128 bf16/row)

__device__ __forceinline__ int edge_idx(const void* p, int e, int is64) {
    if (is64) return (int)((const long long*)p)[e];
    return ((const int*)p)[e];
}

// ---------------- detect dtype + zero counters (merged) ------------------
// Node ids < 10000 < 2^32: if buffer is int64, every odd 32-bit word is 0.
__global__ void detect_zero_kernel(const void* src) {
    int i = blockIdx.x * blockDim.x + threadIdx.x;
    if (i < NN) { g_indeg[i] = 0; g_outdeg[i] = 0; g_fill[i] = 0; }
    if (blockIdx.x == 0) {
        __shared__ int any_nonzero;
        if (threadIdx.x == 0) any_nonzero = 0;
        __syncthreads();
        const int* w = (const int*)src;
#pragma unroll
        for (int it = 0; it < 2; it++) {
            int idx = 2 * (threadIdx.x + it * 256) + 1;
            if (w[idx] != 0) any_nonzero = 1;
        }
        __syncthreads();
        if (threadIdx.x == 0) g_is64 = any_nonzero ? 0 : 1;
    }
}

__global__ void degrees_kernel(const void* __restrict__ src,
                               const void* __restrict__ dst) {
    int e = blockIdx.x * blockDim.x + threadIdx.x;
    int is64 = g_is64;
    if (e < NE) {
        int s = edge_idx(src, e, is64);
        int d = edge_idx(dst, e, is64);
        if ((unsigned)s < NN) atomicAdd(&g_outdeg[s], 1);
        if ((unsigned)d < NN) atomicAdd(&g_indeg[d], 1);
    }
}

// ---------------- norms + row_start scan (merged) -------------------------
// All blocks: per-node norms. Block 0 additionally does the exclusive scan
// of g_indeg (reads only g_indeg, ready at kernel start).
__global__ void norms_scan_kernel() {
    int i = blockIdx.x * blockDim.x + threadIdx.x;
    if (i < NN) {
        g_norm_src[i] = rsqrtf(fmaxf((float)g_outdeg[i], 1.0f));
        g_norm_dst[i] = rsqrtf(fmaxf((float)g_indeg[i], 1.0f));
    }
    if (blockIdx.x == 0) {
        __shared__ int ssum[256];
        const int CH = 40;            // 256 * 40 = 10240 >= NN
        int t = threadIdx.x;
        int base = t * CH;
        int s = 0;
#pragma unroll 8
        for (int k = 0; k < CH; k++) {
            int idx = base + k;
            s += (idx < NN) ? g_indeg[idx] : 0;
        }
        ssum[t] = s;
        __syncthreads();
        for (int off = 1; off < 256; off <<= 1) {
            int add = (t >= off) ? ssum[t - off] : 0;
            __syncthreads();
            ssum[t] += add;
            __syncthreads();
        }
        int run = (t > 0) ? ssum[t - 1] : 0;
#pragma unroll 8
        for (int k = 0; k < CH; k++) {
            int idx = base + k;
            if (idx < NN) {
                g_row_start[idx] = run;
                run += g_indeg[idx];
            }
        }
        if (t == 255) g_row_start[NN] = ssum[255];
    }
}

__global__ void fill_kernel(const void* __restrict__ src,
                            const void* __restrict__ dst) {
    int e = blockIdx.x * blockDim.x + threadIdx.x;
    int is64 = g_is64;
    if (e < NE) {
        int d = edge_idx(dst, e, is64);
        int s = edge_idx(src, e, is64);
        if ((unsigned)d < NN && (unsigned)s < NN) {
            int pos = g_row_start[d] + atomicAdd(&g_fill[d], 1);
            g_edge[pos] = make_int2(s, __float_as_int(g_norm_src[s]));
        }
    }
}

// ---------------- SpMM (fp32 gather): layer 1 only ----------------------
// Edge list staged per-warp into smem with coalesced loads (2 LDG per 64-edge
// chunk) so the gather loop's only long-latency op is the gather itself.
__global__ void __launch_bounds__(256) spmm_fp32_kernel(const float* __restrict__ X) {
    __shared__ int2 se[8][64];
    int wid = threadIdx.x >> 5;
    int warp = blockIdx.x * 8 + wid;
    if (warp >= NN) return;
    int lane = threadIdx.x & 31;
    int j0 = g_row_start[warp];
    int j1 = g_row_start[warp + 1];
    const float4* __restrict__ Xv = (const float4*)X;
    const int2*   __restrict__ Ev = g_edge;

    float4 a0 = make_float4(0.f, 0.f, 0.f, 0.f);
    float4 a1 = make_float4(0.f, 0.f, 0.f, 0.f);
    float4 a2 = make_float4(0.f, 0.f, 0.f, 0.f);
    float4 a3 = make_float4(0.f, 0.f, 0.f, 0.f);

    for (int jc = j0; jc < j1; jc += 64) {
        int n = min(64, j1 - jc);
        if (lane < n)      se[wid][lane]      = Ev[jc + lane];
        if (lane + 32 < n) se[wid][lane + 32] = Ev[jc + lane + 32];
        __syncwarp();
        int k = 0;
        for (; k + 8 <= n; k += 8) {
            int2 e0 = se[wid][k+0], e1 = se[wid][k+1], e2 = se[wid][k+2], e3 = se[wid][k+3];
            int2 e4 = se[wid][k+4], e5 = se[wid][k+5], e6 = se[wid][k+6], e7 = se[wid][k+7];
            float4 v0 = Xv[e0.x * 32 + lane];
            float4 v1 = Xv[e1.x * 32 + lane];
            float4 v2 = Xv[e2.x * 32 + lane];
            float4 v3 = Xv[e3.x * 32 + lane];
            float4 v4 = Xv[e4.x * 32 + lane];
            float4 v5 = Xv[e5.x * 32 + lane];
            float4 v6 = Xv[e6.x * 32 + lane];
            float4 v7 = Xv[e7.x * 32 + lane];
            float n0 = __int_as_float(e0.y), n1 = __int_as_float(e1.y);
            float n2 = __int_as_float(e2.y), n3 = __int_as_float(e3.y);
            float n4 = __int_as_float(e4.y), n5 = __int_as_float(e5.y);
            float n6 = __int_as_float(e6.y), n7 = __int_as_float(e7.y);
            a0.x += v0.x * n0; a0.y += v0.y * n0; a0.z += v0.z * n0; a0.w += v0.w * n0;
            a1.x += v1.x * n1; a1.y += v1.y * n1; a1.z += v1.z * n1; a1.w += v1.w * n1;
            a2.x += v2.x * n2; a2.y += v2.y * n2; a2.z += v2.z * n2; a2.w += v2.w * n2;
            a3.x += v3.x * n3; a3.y += v3.y * n3; a3.z += v3.z * n3; a3.w += v3.w * n3;
            a0.x += v4.x * n4; a0.y += v4.y * n4; a0.z += v4.z * n4; a0.w += v4.w * n4;
            a1.x += v5.x * n5; a1.y += v5.y * n5; a1.z += v5.z * n5; a1.w += v5.w * n5;
            a2.x += v6.x * n6; a2.y += v6.y * n6; a2.z += v6.z * n6; a2.w += v6.w * n6;
            a3.x += v7.x * n7; a3.y += v7.y * n7; a3.z += v7.z * n7; a3.w += v7.w * n7;
        }
        for (; k < n; ++k) {
            int2 e = se[wid][k];
            float nv = __int_as_float(e.y);
            float4 v = Xv[e.x * 32 + lane];
            a0.x += v.x * nv; a0.y += v.y * nv; a0.z += v.z * nv; a0.w += v.w * nv;
        }
        __syncwarp();
    }

    float nd = g_norm_dst[warp];
    float4 acc;
    acc.x = (a0.x + a1.x + a2.x + a3.x) * nd;
    acc.y = (a0.y + a1.y + a2.y + a3.y) * nd;
    acc.z = (a0.z + a1.z + a2.z + a3.z) * nd;
    acc.w = (a0.w + a1.w + a2.w + a3.w) * nd;
    ((float4*)g_agg)[warp * 32 + lane] = acc;
}

// ---------------- SpMM (bf16 gather): layers 2-6 ------------------------
__global__ void __launch_bounds__(256) spmm_bf16_kernel() {
    __shared__ int2 se[8][64];
    int wid = threadIdx.x >> 5;
    int warp = blockIdx.x * 8 + wid;
    if (warp >= NN) return;
    int lane = threadIdx.x & 31;
    int j0 = g_row_start[warp];
    int j1 = g_row_start[warp + 1];
    const uint2* __restrict__ Xv = g_x16;
    const int2*  __restrict__ Ev = g_edge;

    float4 a0 = make_float4(0.f, 0.f, 0.f, 0.f);
    float4 a1 = make_float4(0.f, 0.f, 0.f, 0.f);
    float4 a2 = make_float4(0.f, 0.f, 0.f, 0.f);
    float4 a3 = make_float4(0.f, 0.f, 0.f, 0.f);

    for (int jc = j0; jc < j1; jc += 64) {
        int n = min(64, j1 - jc);
        if (lane < n)      se[wid][lane]      = Ev[jc + lane];
        if (lane + 32 < n) se[wid][lane + 32] = Ev[jc + lane + 32];
        __syncwarp();
        int k = 0;
        for (; k + 8 <= n; k += 8) {
            int2 e0 = se[wid][k+0], e1 = se[wid][k+1], e2 = se[wid][k+2], e3 = se[wid][k+3];
            int2 e4 = se[wid][k+4], e5 = se[wid][k+5], e6 = se[wid][k+6], e7 = se[wid][k+7];
            uint2 v0 = Xv[e0.x * 32 + lane];
            uint2 v1 = Xv[e1.x * 32 + lane];
            uint2 v2 = Xv[e2.x * 32 + lane];
            uint2 v3 = Xv[e3.x * 32 + lane];
            uint2 v4 = Xv[e4.x * 32 + lane];
            uint2 v5 = Xv[e5.x * 32 + lane];
            uint2 v6 = Xv[e6.x * 32 + lane];
            uint2 v7 = Xv[e7.x * 32 + lane];
            float n0 = __int_as_float(e0.y), n1 = __int_as_float(e1.y);
            float n2 = __int_as_float(e2.y), n3 = __int_as_float(e3.y);
            float n4 = __int_as_float(e4.y), n5 = __int_as_float(e5.y);
            float n6 = __int_as_float(e6.y), n7 = __int_as_float(e7.y);
#define ACC(A, V, NV) { \
            float2 lo = __bfloat1622float2(*(__nv_bfloat162*)&(V).x); \
            float2 hi = __bfloat1622float2(*(__nv_bfloat162*)&(V).y); \
            (A).x += lo.x * (NV); (A).y += lo.y * (NV); \
            (A).z += hi.x * (NV); (A).w += hi.y * (NV); }
            ACC(a0, v0, n0) ACC(a1, v1, n1) ACC(a2, v2, n2) ACC(a3, v3, n3)
            ACC(a0, v4, n4) ACC(a1, v5, n5) ACC(a2, v6, n6) ACC(a3, v7, n7)
        }
        for (; k < n; ++k) {
            int2 e = se[wid][k];
            float nv = __int_as_float(e.y);
            uint2 v = Xv[e.x * 32 + lane];
            ACC(a0, v, nv)
        }
#undef ACC
        __syncwarp();
    }

    float nd = g_norm_dst[warp];
    float4 acc;
    acc.x = (a0.x + a1.x + a2.x + a3.x) * nd;
    acc.y = (a0.y + a1.y + a2.y + a3.y) * nd;
    acc.z = (a0.z + a1.z + a2.z + a3.z) * nd;
    acc.w = (a0.w + a1.w + a2.w + a3.w) * nd;
    ((float4*)g_agg)[warp * 32 + lane] = acc;
}

// ---------------- GEMM: Y[M,128] = g_agg[M,128] @ W[128,128] + b (opt. ReLU)
// Epilogue also writes the bf16 copy (g_x16) for the next layer's gather.
// 64x64 tile per block, 256 threads (16x16), 4x4 microtile per thread.
__global__ void __launch_bounds__(256, 4) gemm_kernel(const float* __restrict__ W,
                            const float* __restrict__ b,
                            float* __restrict__ Y,
                            int relu) {
    __shared__ float As[16][64];   // [k][row]
    __shared__ float Ws[16][64];   // [k][col]
    const float* __restrict__ A = g_agg;
    int t  = threadIdx.x;
    int tx = t & 15;
    int ty = t >> 4;
    int rb = blockIdx.x * 64;
    int cb = blockIdx.y * 64;

    float acc[4][4];
#pragma unroll
    for (int i = 0; i < 4; i++)
#pragma unroll
        for (int j = 0; j < 4; j++) acc[i][j] = 0.f;

    for (int kb = 0; kb < DD; kb += 16) {
        // load A tile: 64 rows x 16 k -> As[k][row]
#pragma unroll
        for (int it = 0; it < 4; it++) {
            int idx = t + it * 256;       // 0..1023
            int row = idx >> 4;
            int kk  = idx & 15;
            int gr  = rb + row;
            As[kk][row] = (gr < NN) ? A[gr * DD + kb + kk] : 0.f;
        }
        // load W tile: 16 k x 64 cols -> Ws[k][col]
#pragma unroll
        for (int it = 0; it < 4; it++) {
            int idx = t + it * 256;
            int k = idx >> 6;
            int c = idx & 63;
            Ws[k][c] = W[(kb + k) * DD + cb + c];
        }
        __syncthreads();
#pragma unroll
        for (int k = 0; k < 16; k++) {
            float4 a = *(const float4*)&As[k][ty * 4];
            float4 w = *(const float4*)&Ws[k][tx * 4];
            acc[0][0] += a.x * w.x; acc[0][1] += a.x * w.y; acc[0][2] += a.x * w.z; acc[0][3] += a.x * w.w;
            acc[1][0] += a.y * w.x; acc[1][1] += a.y * w.y; acc[1][2] += a.y * w.z; acc[1][3] += a.y * w.w;
            acc[2][0] += a.z * w.x; acc[2][1] += a.z * w.y; acc[2][2] += a.z * w.z; acc[2][3] += a.z * w.w;
            acc[3][0] += a.w * w.x; acc[3][1] += a.w * w.y; acc[3][2] += a.w * w.z; acc[3][3] += a.w * w.w;
        }
        __syncthreads();
    }

    int c0 = cb + tx * 4;
    float4 bias = *(const float4*)&b[c0];
#pragma unroll
    for (int i = 0; i < 4; i++) {
        int r = rb + ty * 4 + i;
        if (r < NN) {
            float4 o;
            o.x = acc[i][0] + bias.x;
            o.y = acc[i][1] + bias.y;
            o.z = acc[i][2] + bias.z;
            o.w = acc[i][3] + bias.w;
            if (relu) {
                o.x = fmaxf(o.x, 0.f); o.y = fmaxf(o.y, 0.f);
                o.z = fmaxf(o.z, 0.f); o.w = fmaxf(o.w, 0.f);
            }
            *(float4*)&Y[r * DD + c0] = o;
            // bf16 copy for next layer's gather
            __nv_bfloat162 b0 = __float22bfloat162_rn(make_float2(o.x, o.y));
            __nv_bfloat162 b1 = __float22bfloat162_rn(make_float2(o.z, o.w));
            uint2 pk;
            pk.x = *(unsigned*)&b0;
            pk.y = *(unsigned*)&b1;
            g_x16[r * 32 + (c0 >> 2)] = pk;
        }
    }
}

// ---------------- launch ----------------
extern "C" void kernel_launch(void* const* d_in, const int* in_sizes, int n_in,
                              void* d_out, int out_size) {
    const float* x   = (const float*)d_in[0];
    const void*  src = d_in[1];   // int32 or int64 — detected on device
    const void*  dst = d_in[2];
    const float* W[6] = { (const float*)d_in[3], (const float*)d_in[5],
                          (const float*)d_in[7], (const float*)d_in[9],
                          (const float*)d_in[11], (const float*)d_in[13] };
    const float* B[6] = { (const float*)d_in[4], (const float*)d_in[6],
                          (const float*)d_in[8], (const float*)d_in[10],
                          (const float*)d_in[12], (const float*)d_in[14] };
    float* out = (float*)d_out;

    // output layout: (h6, h5, h4, h3, h2, h1)
    float* h[6];
    for (int i = 0; i < 6; i++) h[i] = out + (size_t)(5 - i) * ND;  // h[0]=h1 ... h[5]=h6

    // graph build (4 launches)
    detect_zero_kernel<<<(NN + 255) / 256, 256>>>(src);
    degrees_kernel<<<(NE + 255) / 256, 256>>>(src, dst);
    norms_scan_kernel<<<(NN + 255) / 256, 256>>>();
    fill_kernel<<<(NE + 255) / 256, 256>>>(src, dst);

    dim3 gemm_grid((NN + 63) / 64, 2);
    const int SPMM_BLK = 256;                      // 8 warps/block
    int spmm_grid = (NN + 7) / 8;                  // one warp per row

    for (int layer = 0; layer < 6; layer++) {
        if (layer == 0)
            spmm_fp32_kernel<<<spmm_grid, SPMM_BLK>>>(x);
        else
            spmm_bf16_kernel<<<spmm_grid, SPMM_BLK>>>();
        gemm_kernel<<<gemm_grid, 256>>>(W[layer], B[layer], h[layer],
                                        layer < 5 ? 1 : 0);
    }
}